// round 4
// baseline (speedup 1.0000x reference)
#include <cuda_runtime.h>
#include <cstdint>

// HarmonicLowering: out[b, k*32 + c, f, t] = w*x[b,c,idx,t] + (1-w)*x[b,c,idx1,t]
//   idx = f*(k+1)>>2, rem = (f*(k+1))&3, w = 1 - rem/4, idx1 = min(idx+1, 255)
// x (8,32,256,512) fp32 -> out (8,128,256,512) fp32.
// 4 float4 per thread (quarter-row stride) for high MLP; __stcs streaming
// stores protect L2-resident input against the 537MB output stream.

static constexpr int BATCH = 8;
static constexpr int C     = 32;
static constexpr int FREQ  = 256;
static constexpr int TIME  = 512;
static constexpr int T4    = TIME / 4;      // 128 float4 per row
static constexpr int T4Q   = T4 / 4;        // 32: quarter-row, 4 per thread
static constexpr long long TOTAL_THREADS =
    (long long)BATCH * (4 * C) * FREQ * T4Q;  // 8,388,608

__global__ void __launch_bounds__(256)
harmonic_lowering_kernel(const float4* __restrict__ x4, float4* __restrict__ out4)
{
    unsigned int tid = blockIdx.x * blockDim.x + threadIdx.x;

    // Decode: [b (3b)][kc (7b)][f (8b)][t4q (5b)]
    unsigned int t4q = tid & (T4Q - 1);
    unsigned int r   = tid >> 5;
    unsigned int f   = r & (FREQ - 1);
    r >>= 8;
    unsigned int kc  = r & 127;     // k*32 + c
    unsigned int b   = r >> 7;

    unsigned int k   = kc >> 5;     // ks = k+1
    unsigned int c   = kc & 31;

    unsigned int prod = f * (k + 1);
    unsigned int idx  = prod >> 2;
    unsigned int rem  = prod & 3;
    unsigned int idx1 = (idx + 1 < FREQ) ? idx + 1 : FREQ - 1;

    unsigned int plane = (b * C + c) * (FREQ * T4);
    unsigned int r0 = plane + idx  * T4 + t4q;
    unsigned int r1 = plane + idx1 * T4 + t4q;

    unsigned int obase = ((((b << 7) | kc) << 8) | f) * T4 + t4q;

    if (rem == 0) {
        // Pure copy rows (50% of all rows)
        float4 a0 = x4[r0];
        float4 a1 = x4[r0 +     T4Q];
        float4 a2 = x4[r0 + 2 * T4Q];
        float4 a3 = x4[r0 + 3 * T4Q];
        __stcs(&out4[obase],           a0);
        __stcs(&out4[obase +     T4Q], a1);
        __stcs(&out4[obase + 2 * T4Q], a2);
        __stcs(&out4[obase + 3 * T4Q], a3);
    } else {
        float w  = 1.0f - 0.25f * (float)rem;
        float w1 = 1.0f - w;
        float4 g0a = x4[r0];
        float4 g1a = x4[r1];
        float4 g0b = x4[r0 +     T4Q];
        float4 g1b = x4[r1 +     T4Q];
        float4 g0c = x4[r0 + 2 * T4Q];
        float4 g1c = x4[r1 + 2 * T4Q];
        float4 g0d = x4[r0 + 3 * T4Q];
        float4 g1d = x4[r1 + 3 * T4Q];
        float4 o;
        o.x = fmaf(w, g0a.x, w1 * g1a.x);
        o.y = fmaf(w, g0a.y, w1 * g1a.y);
        o.z = fmaf(w, g0a.z, w1 * g1a.z);
        o.w = fmaf(w, g0a.w, w1 * g1a.w);
        __stcs(&out4[obase], o);
        o.x = fmaf(w, g0b.x, w1 * g1b.x);
        o.y = fmaf(w, g0b.y, w1 * g1b.y);
        o.z = fmaf(w, g0b.z, w1 * g1b.z);
        o.w = fmaf(w, g0b.w, w1 * g1b.w);
        __stcs(&out4[obase + T4Q], o);
        o.x = fmaf(w, g0c.x, w1 * g1c.x);
        o.y = fmaf(w, g0c.y, w1 * g1c.y);
        o.z = fmaf(w, g0c.z, w1 * g1c.z);
        o.w = fmaf(w, g0c.w, w1 * g1c.w);
        __stcs(&out4[obase + 2 * T4Q], o);
        o.x = fmaf(w, g0d.x, w1 * g1d.x);
        o.y = fmaf(w, g0d.y, w1 * g1d.y);
        o.z = fmaf(w, g0d.z, w1 * g1d.z);
        o.w = fmaf(w, g0d.w, w1 * g1d.w);
        __stcs(&out4[obase + 3 * T4Q], o);
    }
}

extern "C" void kernel_launch(void* const* d_in, const int* in_sizes, int n_in,
                              void* d_out, int out_size)
{
    const float4* x4 = (const float4*)d_in[0];
    float4* out4 = (float4*)d_out;
    const int threads = 256;
    const int blocks = (int)(TOTAL_THREADS / threads);   // 32768
    harmonic_lowering_kernel<<<blocks, threads>>>(x4, out4);
}